// round 16
// baseline (speedup 1.0000x reference)
#include <cuda_runtime.h>
#include <cuda_bf16.h>
#include <math.h>

#define BSZ   4
#define TSEQ  1024
#define CDIM  1024
#define NHEAD 16
#define DHEAD 64

typedef unsigned long long u64;

#if defined(__CUDA_ARCH_FEAT_SM103_ALL) || \
    (defined(__CUDA_ARCH_SPECIFIC__) && (__CUDA_ARCH_SPECIFIC__ == 1030))
#define HAS_TCGEN05 1
#else
#define HAS_TCGEN05 0
#endif

// ---------------- scratch (allocation-free: __device__ globals) -------------
__device__ float g_qkv[BSZ * TSEQ * 3 * CDIM];
__device__ float g_G[BSZ * NHEAD * TSEQ * TSEQ];          // 268MB: q_t . embk[d]
__device__ __nv_bfloat16 g_xh[BSZ * TSEQ * CDIM], g_xl[BSZ * TSEQ * CDIM];
__device__ __nv_bfloat16 g_wah[3 * CDIM * CDIM], g_wal[3 * CDIM * CDIM]; // [N,K]
__device__ __nv_bfloat16 g_wph[CDIM * CDIM],     g_wpl[CDIM * CDIM];     // [N,K]
__device__ __nv_bfloat16 g_yh[BSZ * TSEQ * CDIM], g_yl[BSZ * TSEQ * CDIM];
__device__ __nv_bfloat16 g_qph[BSZ * NHEAD * TSEQ * DHEAD];
__device__ __nv_bfloat16 g_qpl[BSZ * NHEAD * TSEQ * DHEAD];
__device__ __nv_bfloat16 g_ebh[TSEQ * DHEAD], g_ebl[TSEQ * DHEAD];

// ---------------- packed f32x2 helpers --------------------------------------
__device__ __forceinline__ u64 ffma2(u64 a, u64 b, u64 c) {
  u64 d; asm("fma.rn.f32x2 %0, %1, %2, %3;" : "=l"(d) : "l"(a), "l"(b), "l"(c));
  return d;
}
__device__ __forceinline__ u64 fadd2(u64 a, u64 b) {
  u64 d; asm("add.rn.f32x2 %0, %1, %2;" : "=l"(d) : "l"(a), "l"(b));
  return d;
}
__device__ __forceinline__ u64 fmul2(u64 a, u64 b) {
  u64 d; asm("mul.rn.f32x2 %0, %1, %2;" : "=l"(d) : "l"(a), "l"(b));
  return d;
}
__device__ __forceinline__ u64 fpack2(float lo, float hi) {
  u64 d; asm("mov.b64 %0, {%1, %2};" : "=l"(d) : "f"(lo), "f"(hi));
  return d;
}
__device__ __forceinline__ void funpack2(float& lo, float& hi, u64 d) {
  asm("mov.b64 {%0, %1}, %2;" : "=f"(lo), "=f"(hi) : "l"(d));
}
__device__ __forceinline__ unsigned bfpack(__nv_bfloat16 a, __nv_bfloat16 b) {
  __nv_bfloat162 t(a, b);
  return *(unsigned*)&t;
}

// ---------------- generic plumbing ------------------------------------------
__device__ __forceinline__ unsigned smem_u32(const void* p) {
  unsigned a;
  asm("{ .reg .u64 t; cvta.to.shared.u64 t, %1; cvt.u32.u64 %0, t; }"
      : "=r"(a) : "l"(p));
  return a;
}
__device__ __forceinline__ unsigned elect_one() {
  unsigned p;
  asm volatile("{ .reg .pred P; elect.sync _|P, 0xFFFFFFFF; selp.b32 %0,1,0,P; }"
               : "=r"(p));
  return p;
}
__device__ __forceinline__ void cp_async16(unsigned dst, const void* src) {
  asm volatile("cp.async.cg.shared.global [%0], [%1], 16;"
               :: "r"(dst), "l"(src) : "memory");
}
#define CP_COMMIT() asm volatile("cp.async.commit_group;" ::: "memory")
#define CP_WAIT(n)  asm volatile("cp.async.wait_group %0;" :: "n"(n) : "memory")

__device__ __forceinline__ void mbar_init(unsigned a, unsigned cnt) {
  asm volatile("mbarrier.init.shared.b64 [%0], %1;" :: "r"(a), "r"(cnt) : "memory");
}
__device__ __forceinline__ void mbar_wait(unsigned a, unsigned phase) {
  asm volatile(
      "{\n\t.reg .pred P;\n\t"
      "W_%=:\n\t"
      "mbarrier.try_wait.parity.acquire.cta.shared::cta.b64 P, [%0], %1, 0x989680;\n\t"
      "@!P bra W_%=;\n\t}"
      :: "r"(a), "r"(phase) : "memory");
}

#define SWZ128(o) ((o) ^ (((o) >> 3) & 0x70))
__device__ __forceinline__ u64 make_desc(unsigned addr) {
  const u64 base = (2ull << 61) | (1ull << 46) | (64ull << 32) | (1ull << 16);
  return base | ((u64)(addr >> 4) & 0x3FFF);
}
// idesc: c=F32, a=BF16, b=BF16, M=128, N=256
#define GEMM_IDESC ((1u<<4)|(1u<<7)|(1u<<10)|((256u/8)<<17)|((128u/16)<<24))

// ---------------- tcgen05 wrappers (sm_103a pass only) ----------------------
#if HAS_TCGEN05
__device__ __forceinline__ void tmem_alloc(unsigned smem_dst, unsigned ncols) {
  asm volatile("tcgen05.alloc.cta_group::1.sync.aligned.shared::cta.b32 [%0], %1;"
               :: "r"(smem_dst), "r"(ncols) : "memory");
}
__device__ __forceinline__ void tmem_dealloc(unsigned tmem, unsigned ncols) {
  asm volatile("tcgen05.dealloc.cta_group::1.sync.aligned.b32 %0, %1;"
               :: "r"(tmem), "r"(ncols));
}
__device__ __forceinline__ void tmem_relinquish() {
  asm volatile("tcgen05.relinquish_alloc_permit.cta_group::1.sync.aligned;");
}
__device__ __forceinline__ void tc_commit(unsigned mbar) {
  asm volatile(
      "tcgen05.commit.cta_group::1.mbarrier::arrive::one.shared::cluster.b64 [%0];"
      :: "r"(mbar) : "memory");
}
#define TC_FENCE_AFTER()  asm volatile("tcgen05.fence::after_thread_sync;" ::: "memory")
#define TC_WAIT_LD()      asm volatile("tcgen05.wait::ld.sync.aligned;" ::: "memory")

__device__ __forceinline__ void mma_f16_ss(unsigned d_tmem, u64 a_desc, u64 b_desc,
                                           unsigned idesc, unsigned enable) {
  asm volatile(
      "{\n\t.reg .pred p;\n\tsetp.ne.u32 p, %4, 0;\n\t"
      "tcgen05.mma.cta_group::1.kind::f16 [%0], %1, %2, %3, {%5,%5,%5,%5}, p;\n\t}"
      :: "r"(d_tmem), "l"(a_desc), "l"(b_desc), "r"(idesc), "r"(enable), "r"(0u)
      : "memory");
}
__device__ __forceinline__ void tmem_ld32(unsigned* r, unsigned addr) {
  asm volatile(
      "tcgen05.ld.sync.aligned.32x32b.x32.b32 "
      "{%0,%1,%2,%3,%4,%5,%6,%7,%8,%9,%10,%11,%12,%13,%14,%15,"
      "%16,%17,%18,%19,%20,%21,%22,%23,%24,%25,%26,%27,%28,%29,%30,%31}, [%32];"
      : "=r"(r[0]),"=r"(r[1]),"=r"(r[2]),"=r"(r[3]),"=r"(r[4]),"=r"(r[5]),
        "=r"(r[6]),"=r"(r[7]),"=r"(r[8]),"=r"(r[9]),"=r"(r[10]),"=r"(r[11]),
        "=r"(r[12]),"=r"(r[13]),"=r"(r[14]),"=r"(r[15]),"=r"(r[16]),"=r"(r[17]),
        "=r"(r[18]),"=r"(r[19]),"=r"(r[20]),"=r"(r[21]),"=r"(r[22]),"=r"(r[23]),
        "=r"(r[24]),"=r"(r[25]),"=r"(r[26]),"=r"(r[27]),"=r"(r[28]),"=r"(r[29]),
        "=r"(r[30]),"=r"(r[31])
      : "r"(addr));
}
#endif  // HAS_TCGEN05

// ---------------------------------------------------------------------------
// Unified GEMM: 128x256 tile, tcgen05 bf16x3 on sm_103a, FFMA2 fp32 fallback.
// tri != 0  : C rows encode t = row & 1023; stores masked to col <= t, and
//             CTAs with bcol0 > t_max exit immediately (triangular G).
// qh/ql set : columns < 1024 additionally emitted as bf16 hi/lo in packed-Q
//             layout [b*16+h][t][d] (fused qpack).
// ---------------------------------------------------------------------------
#define A_TILE  (128 * 64 * 2)
#define B_TILE  (256 * 64 * 2)
#define G_BUF   (2 * A_TILE + 2 * B_TILE)
#define G_SMEM  (1024 + 2 * G_BUF)

__global__ void __launch_bounds__(256) gemm_kernel(
    const __nv_bfloat16* __restrict__ Ah, const __nv_bfloat16* __restrict__ Al,
    const __nv_bfloat16* __restrict__ Bh, const __nv_bfloat16* __restrict__ Bl,
    const float* __restrict__ Af, const float* __restrict__ Bf,
    float* __restrict__ C,
    __nv_bfloat16* __restrict__ qh, __nv_bfloat16* __restrict__ ql,
    int tri, int M, int N, int K) {
  extern __shared__ char smem[];
  const int tid = threadIdx.x;
  const int brow = blockIdx.y * 128, bcol0 = blockIdx.x * 256;

  // triangular early exit: whole tile above the diagonal band is never read
  if (tri && bcol0 > ((brow & 1023) + 127)) return;

#if HAS_TCGEN05
  const unsigned sb = smem_u32(smem);
  const int wid = tid >> 5, lid = tid & 31;
  const int NKT = K >> 6;
  const unsigned mb0 = sb + 16, mb1 = sb + 24;
  const unsigned tiles = sb + 1024;

  if (tid == 0) { mbar_init(mb0, 1); mbar_init(mb1, 1); }
  if (wid == 0) { tmem_alloc(sb, 256); tmem_relinquish(); }
  __syncthreads();
  unsigned tmem;
  asm volatile("ld.shared.b32 %0, [%1];" : "=r"(tmem) : "r"(sb));

  auto stage1 = [&](unsigned dstbase, const __nv_bfloat16* src, int nrows) {
    const int lines = nrows * 8;
#pragma unroll 8
    for (int i = tid; i < lines; i += 256) {
      int r = i >> 3, c = i & 7;
      cp_async16(dstbase + SWZ128(r * 128 + c * 16), src + (size_t)r * K + c * 8);
    }
  };
  auto stage = [&](int buf, int kt) {
    unsigned base = tiles + buf * G_BUF;
    stage1(base,                       Ah + (size_t)brow * K + kt * 64, 128);
    stage1(base + A_TILE,              Al + (size_t)brow * K + kt * 64, 128);
    stage1(base + 2 * A_TILE,          Bh + (size_t)bcol0 * K + kt * 64, 256);
    stage1(base + 2 * A_TILE + B_TILE, Bl + (size_t)bcol0 * K + kt * 64, 256);
  };

  stage(0, 0);
  CP_COMMIT();
  int ph0 = 0, ph1 = 0;

  for (int kt = 0; kt < NKT; kt++) {
    const int buf = kt & 1;
    if (kt > 0) {
      if (((kt - 1) & 1) == 0) { mbar_wait(mb0, ph0 & 1); ph0++; }
      else                     { mbar_wait(mb1, ph1 & 1); ph1++; }
    }
    if (kt + 1 < NKT) { stage(buf ^ 1, kt + 1); CP_COMMIT(); CP_WAIT(1); }
    else              { CP_WAIT(0); }
    __syncthreads();

    if (wid == 0 && elect_one()) {
      asm volatile("fence.proxy.async.shared::cta;" ::: "memory");
      unsigned base = tiles + buf * G_BUF;
      u64 dAh = make_desc(base),              dAl = make_desc(base + A_TILE);
      u64 dBh = make_desc(base + 2 * A_TILE), dBl = make_desc(base + 2 * A_TILE + B_TILE);
      u64 da[3] = {dAh, dAl, dAh};
      u64 db[3] = {dBh, dBh, dBl};
#pragma unroll
      for (int p = 0; p < 3; p++)
#pragma unroll
        for (int ks = 0; ks < 4; ks++)
          mma_f16_ss(tmem, da[p] + ks * 2, db[p] + ks * 2, GEMM_IDESC,
                     !(kt == 0 && p == 0 && ks == 0));
      tc_commit(buf == 0 ? mb0 : mb1);
    }
  }
  if (((NKT - 1) & 1) == 0) { mbar_wait(mb0, ph0 & 1); }
  else                      { mbar_wait(mb1, ph1 & 1); }
  TC_FENCE_AFTER();

  if (wid < 4) {
    const size_t row = (size_t)brow + wid * 32 + lid;
    const int trow = (int)(row & 1023);
    const bool do_q = (qh != nullptr) && (bcol0 < 1024);
    size_t qrowbase = 0;
    if (do_q) {
      int bb = (int)(row >> 10);
      qrowbase = ((size_t)bb * NHEAD) * TSEQ + trow;   // + h*TSEQ added per col
    }
#pragma unroll
    for (int cb = 0; cb < 256; cb += 32) {
      unsigned r[32];
      tmem_ld32(r, tmem + cb);
      TC_WAIT_LD();
      float* dst = &C[row * N + bcol0 + cb];
      if (!tri) {
#pragma unroll
        for (int c = 0; c < 32; c += 4)
          *(float4*)&dst[c] = make_float4(__uint_as_float(r[c]), __uint_as_float(r[c+1]),
                                          __uint_as_float(r[c+2]), __uint_as_float(r[c+3]));
        if (do_q) {
#pragma unroll
          for (int c = 0; c < 32; c += 4) {
            int cg = bcol0 + cb + c;          // global col, < 1024, mult of 4
            int hh = cg >> 6, dd = cg & 63;
            size_t off = (qrowbase + (size_t)hh * TSEQ) * DHEAD + dd;
            float v0 = __uint_as_float(r[c]),   v1 = __uint_as_float(r[c+1]);
            float v2 = __uint_as_float(r[c+2]), v3 = __uint_as_float(r[c+3]);
            __nv_bfloat16 h0 = __float2bfloat16_rn(v0), h1 = __float2bfloat16_rn(v1);
            __nv_bfloat16 h2 = __float2bfloat16_rn(v2), h3 = __float2bfloat16_rn(v3);
            __nv_bfloat16 l0 = __float2bfloat16_rn(v0 - __bfloat162float(h0));
            __nv_bfloat16 l1 = __float2bfloat16_rn(v1 - __bfloat162float(h1));
            __nv_bfloat16 l2 = __float2bfloat16_rn(v2 - __bfloat162float(h2));
            __nv_bfloat16 l3 = __float2bfloat16_rn(v3 - __bfloat162float(h3));
            uint2 uh = make_uint2(bfpack(h0, h1), bfpack(h2, h3));
            uint2 ul = make_uint2(bfpack(l0, l1), bfpack(l2, l3));
            *(uint2*)&qh[off] = uh;
            *(uint2*)&ql[off] = ul;
          }
        }
      } else {
        // masked stores: only cols <= trow are ever read
#pragma unroll
        for (int c = 0; c < 32; c += 4) {
          int dbase = bcol0 + cb + c;
          if (dbase + 3 <= trow) {
            *(float4*)&dst[c] = make_float4(__uint_as_float(r[c]), __uint_as_float(r[c+1]),
                                            __uint_as_float(r[c+2]), __uint_as_float(r[c+3]));
          } else if (dbase <= trow) {
#pragma unroll
            for (int e = 0; e < 4; e++)
              if (dbase + e <= trow) dst[c + e] = __uint_as_float(r[c + e]);
          }
        }
      }
    }
  }
  __syncthreads();
  if (wid == 0) tmem_dealloc(tmem, 256);

#else  // fallback: fp32 FFMA2 SGEMM over the two 128-col halves
  float (*As)[16][132] = reinterpret_cast<float(*)[16][132]>(smem);
  float (*Bs)[16][132] = reinterpret_cast<float(*)[16][132]>(smem + 2 * 16 * 132 * 4);
  const int ty = tid >> 4, tx = tid & 15;
  const int ar0 = tid >> 2,          ac0 = (tid & 3) * 4;
  const int ar1 = (tid + 256) >> 2,  ac1 = ((tid + 256) & 3) * 4;
  const int br0 = tid >> 5,          bc0 = (tid & 31) * 4;
  const int br1 = (tid + 256) >> 5,  bc1 = ((tid + 256) & 31) * 4;

  for (int half = 0; half < 2; half++) {
    const int bcol = bcol0 + half * 128;
    __syncthreads();
    u64 acc2[8][4];
#pragma unroll
    for (int i = 0; i < 8; i++)
#pragma unroll
      for (int j = 0; j < 4; j++) acc2[i][j] = 0ull;

    {
      float4 a0 = *(const float4*)&Af[(size_t)(brow + ar0) * K + ac0];
      float4 a1 = *(const float4*)&Af[(size_t)(brow + ar1) * K + ac1];
      As[0][ac0 + 0][ar0] = a0.x; As[0][ac0 + 1][ar0] = a0.y;
      As[0][ac0 + 2][ar0] = a0.z; As[0][ac0 + 3][ar0] = a0.w;
      As[0][ac1 + 0][ar1] = a1.x; As[0][ac1 + 1][ar1] = a1.y;
      As[0][ac1 + 2][ar1] = a1.z; As[0][ac1 + 3][ar1] = a1.w;
      *(float4*)&Bs[0][br0][bc0] = *(const float4*)&Bf[(size_t)br0 * N + bcol + bc0];
      *(float4*)&Bs[0][br1][bc1] = *(const float4*)&Bf[(size_t)br1 * N + bcol + bc1];
    }
    __syncthreads();

    int buf = 0;
    for (int k0 = 0; k0 < K; k0 += 16) {
      const bool has_next = (k0 + 16) < K;
      float4 pa0, pa1, pb0, pb1;
      if (has_next) {
        pa0 = *(const float4*)&Af[(size_t)(brow + ar0) * K + k0 + 16 + ac0];
        pa1 = *(const float4*)&Af[(size_t)(brow + ar1) * K + k0 + 16 + ac1];
        pb0 = *(const float4*)&Bf[(size_t)(k0 + 16 + br0) * N + bcol + bc0];
        pb1 = *(const float4*)&Bf[(size_t)(k0 + 16 + br1) * N + bcol + bc1];
      }
#pragma unroll
      for (int kk = 0; kk < 16; kk++) {
        float a[8];
        *(float4*)&a[0] = *(float4*)&As[buf][kk][ty * 8];
        *(float4*)&a[4] = *(float4*)&As[buf][kk][ty * 8 + 4];
        u64 b2[4];
        *(ulonglong2*)&b2[0] = *(ulonglong2*)&Bs[buf][kk][tx * 4];
        *(ulonglong2*)&b2[2] = *(ulonglong2*)&Bs[buf][kk][64 + tx * 4];
        u64 ad[8];
#pragma unroll
        for (int i = 0; i < 8; i++) ad[i] = fpack2(a[i], a[i]);
#pragma unroll
        for (int i = 0; i < 8; i++)
#pragma unroll
          for (int j = 0; j < 4; j++) acc2[i][j] = ffma2(ad[i], b2[j], acc2[i][j]);
      }
      if (has_next) {
        int nb = buf ^ 1;
        As[nb][ac0 + 0][ar0] = pa0.x; As[nb][ac0 + 1][ar0] = pa0.y;
        As[nb][ac0 + 2][ar0] = pa0.z; As[nb][ac0 + 3][ar0] = pa0.w;
        As[nb][ac1 + 0][ar1] = pa1.x; As[nb][ac1 + 1][ar1] = pa1.y;
        As[nb][ac1 + 2][ar1] = pa1.z; As[nb][ac1 + 3][ar1] = pa1.w;
        *(float4*)&Bs[nb][br0][bc0] = pb0;
        *(float4*)&Bs[nb][br1][bc1] = pb1;
        __syncthreads();
        buf = nb;
      }
    }
#pragma unroll
    for (int i = 0; i < 8; i++) {
      const int grow = brow + ty * 8 + i;
      size_t r = (size_t)grow * N + bcol;
      const int trow = grow & 1023;
      float v[8];
      funpack2(v[0], v[1], acc2[i][0]); funpack2(v[2], v[3], acc2[i][1]);
      funpack2(v[4], v[5], acc2[i][2]); funpack2(v[6], v[7], acc2[i][3]);
      if (!tri) {
        *(ulonglong2*)&C[r + tx * 4]      = make_ulonglong2(acc2[i][0], acc2[i][1]);
        *(ulonglong2*)&C[r + 64 + tx * 4] = make_ulonglong2(acc2[i][2], acc2[i][3]);
        if (qh && bcol < 1024) {
          int bb = grow >> 10;
#pragma unroll
          for (int e = 0; e < 8; e++) {
            int cg = bcol + (e < 4 ? tx * 4 + e : 64 + tx * 4 + (e - 4));
            int hh = cg >> 6, dd = cg & 63;
            size_t off = (((size_t)bb * NHEAD + hh) * TSEQ + trow) * DHEAD + dd;
            __nv_bfloat16 hv = __float2bfloat16_rn(v[e]);
            qh[off] = hv;
            ql[off] = __float2bfloat16_rn(v[e] - __bfloat162float(hv));
          }
        }
      } else {
#pragma unroll
        for (int e = 0; e < 8; e++) {
          int cg = bcol + (e < 4 ? tx * 4 + e : 64 + tx * 4 + (e - 4));
          if (cg <= trow) C[(size_t)grow * N + cg] = v[e];
        }
      }
    }
  }
#endif
}

// ---------------------------------------------------------------------------
__global__ void __launch_bounds__(256) split_kernel(
    const float* __restrict__ src, __nv_bfloat16* __restrict__ h,
    __nv_bfloat16* __restrict__ l, int n4) {
  int i = blockIdx.x * 256 + threadIdx.x;
  if (i >= n4) return;
  float4 v = ((const float4*)src)[i];
  __nv_bfloat16 h0 = __float2bfloat16_rn(v.x), h1 = __float2bfloat16_rn(v.y);
  __nv_bfloat16 h2 = __float2bfloat16_rn(v.z), h3 = __float2bfloat16_rn(v.w);
  __nv_bfloat16 l0 = __float2bfloat16_rn(v.x - __bfloat162float(h0));
  __nv_bfloat16 l1 = __float2bfloat16_rn(v.y - __bfloat162float(h1));
  __nv_bfloat16 l2 = __float2bfloat16_rn(v.z - __bfloat162float(h2));
  __nv_bfloat16 l3 = __float2bfloat16_rn(v.w - __bfloat162float(h3));
  ((__nv_bfloat162*)h)[i * 2]     = __nv_bfloat162(h0, h1);
  ((__nv_bfloat162*)h)[i * 2 + 1] = __nv_bfloat162(h2, h3);
  ((__nv_bfloat162*)l)[i * 2]     = __nv_bfloat162(l0, l1);
  ((__nv_bfloat162*)l)[i * 2 + 1] = __nv_bfloat162(l2, l3);
}

__global__ void __launch_bounds__(256) splitT_kernel(
    const float* __restrict__ w, __nv_bfloat16* __restrict__ h,
    __nv_bfloat16* __restrict__ l, int K, int N) {
  __shared__ float t[32][33];
  int n0 = blockIdx.x * 32, k0 = blockIdx.y * 32;
  int tx = threadIdx.x, ty = threadIdx.y;
#pragma unroll
  for (int i = 0; i < 32; i += 8)
    t[ty + i][tx] = w[(size_t)(k0 + ty + i) * N + n0 + tx];
  __syncthreads();
#pragma unroll
  for (int i = 0; i < 32; i += 8) {
    float v = t[tx][ty + i];
    __nv_bfloat16 hh = __float2bfloat16_rn(v);
    __nv_bfloat16 ll = __float2bfloat16_rn(v - __bfloat162float(hh));
    size_t o = (size_t)(n0 + ty + i) * K + k0 + tx;
    h[o] = hh; l[o] = ll;
  }
}

// ---------------------------------------------------------------------------
// Flash attention with RPE (R11 verified-optimal structure, unchanged).
// ---------------------------------------------------------------------------
__device__ __forceinline__ int swz(int r, int kk) {
  return r * 64 + ((((kk >> 2) ^ (r >> 2)) & 15) << 2) + (kk & 3);
}

#define ATT_SMEM_FLOATS (3 * 64 * 64 + 128 * 64)
#define ATT_SMEM_BYTES  (ATT_SMEM_FLOATS * 4)

__global__ void __launch_bounds__(256, 2) attn_kernel(
    const float* __restrict__ qkv, const float* __restrict__ G,
    const float* __restrict__ embv,
    __nv_bfloat16* __restrict__ yh, __nv_bfloat16* __restrict__ yl) {
  extern __shared__ float sm[];
  float* Qs  = sm;
  float* Ks  = sm + 64 * 64;
  float* Vs  = sm + 2 * 64 * 64;
  float* Es  = sm + 3 * 64 * 64;

  const int tid = threadIdx.x;
  const int tb = gridDim.x - 1 - blockIdx.x;
  const int h = blockIdx.y, b = blockIdx.z;
  const int t0 = tb * 64;
  const int ty = tid >> 4, tx = tid & 15;
  const int tloc = ty * 4;
  const int cloc = tx * 4;

  const float* Grow[4];
#pragma unroll
  for (int i = 0; i < 4; i++)
    Grow[i] = G + (((size_t)(b * NHEAD + h) * TSEQ) + (t0 + tloc + i)) * TSEQ;

#pragma unroll
  for (int it = 0; it < 4; it++) {
    int g = it * 256 + tid;
    int t = g >> 4, kc = (g & 15) << 2;
    *(float4*)&Qs[swz(t, kc)] =
        *(const float4*)&qkv[(b * TSEQ + t0 + t) * (3 * CDIM) + h * 64 + kc];
  }

  float m_r[4], l_r[4];
#pragma unroll
  for (int i = 0; i < 4; i++) { m_r[i] = -1e30f; l_r[i] = 0.f; }

  u64 accO2[4][2];
#pragma unroll
  for (int i = 0; i < 4; i++) { accO2[i][0] = 0ull; accO2[i][1] = 0ull; }

  for (int sb = 0; sb <= tb; sb++) {
    const int s0 = sb * 64;
    const int diff = t0 - s0;
    __syncthreads();

#pragma unroll
    for (int it = 0; it < 4; it++) {
      int g = it * 256 + tid;
      int s = g >> 4, kc = (g & 15) << 2;
      const float* src = &qkv[(b * TSEQ + s0 + s) * (3 * CDIM) + h * 64 + kc];
      float4 kv = *(const float4*)(src + CDIM);
      float4 vv = *(const float4*)(src + 2 * CDIM);
      kv.x *= 0.125f; kv.y *= 0.125f; kv.z *= 0.125f; kv.w *= 0.125f;
      *(float4*)&Ks[swz(s, kc)] = kv;
      *(float4*)&Vs[swz(s, kc)] = vv;
    }
#pragma unroll
    for (int it = 0; it < 8; it++) {
      int g = it * 256 + tid;
      int j = g >> 4, kc = (g & 15) << 2;
      int rel = diff - 63 + j;
      float4 v = make_float4(0.f, 0.f, 0.f, 0.f);
      if (rel >= 0 && rel < TSEQ) v = *(const float4*)&embv[rel * 64 + kc];
      *(float4*)&Es[swz(j, kc)] = v;
    }
    // gather G band while staging is in flight (independent LDGs)
    float gv[4][4];
    if (sb < tb) {
#pragma unroll
      for (int i = 0; i < 4; i++) {
        int Di = diff + tloc + i - cloc;
#pragma unroll
        for (int j = 0; j < 4; j++) gv[i][j] = Grow[i][Di - j];
      }
    } else {
#pragma unroll
      for (int i = 0; i < 4; i++) {
        int Di = diff + tloc + i - cloc;
#pragma unroll
        for (int j = 0; j < 4; j++) {
          int d = Di - j;
          gv[i][j] = (d >= 0) ? Grow[i][d] : 0.f;
        }
      }
    }
    __syncthreads();

    // ---- S phase: S[t,s] = q . k_scaled (+ G bias) ----
    u64 acc2[4][4];
#pragma unroll
    for (int i = 0; i < 4; i++)
#pragma unroll
      for (int j = 0; j < 4; j++) acc2[i][j] = 0ull;

#pragma unroll 4
    for (int kk = 0; kk < 64; kk += 4) {
      ulonglong2 qd[4], kd[4];
#pragma unroll
      for (int i = 0; i < 4; i++) qd[i] = *(ulonglong2*)&Qs[swz(tloc + i, kk)];
#pragma unroll
      for (int j = 0; j < 4; j++) kd[j] = *(ulonglong2*)&Ks[swz(cloc + j, kk)];
#pragma unroll
      for (int i = 0; i < 4; i++)
#pragma unroll
        for (int j = 0; j < 4; j++) {
          acc2[i][j] = ffma2(qd[i].x, kd[j].x, acc2[i][j]);
          acc2[i][j] = ffma2(qd[i].y, kd[j].y, acc2[i][j]);
        }
    }
    float sv[4][4];
#pragma unroll
    for (int i = 0; i < 4; i++)
#pragma unroll
      for (int j = 0; j < 4; j++) {
        float lo, hi; funpack2(lo, hi, acc2[i][j]);
        bool masked = (sb == tb) && (cloc + j > tloc + i);
        sv[i][j] = masked ? -1e30f : (lo + hi + gv[i][j]);
      }
    __syncthreads();   // all S-phase Ks reads done -> Ks reusable as PT

    // ---- register softmax (16-lane row groups) ----
    float c_r[4];
#pragma unroll
    for (int i = 0; i < 4; i++) {
      float mx = fmaxf(fmaxf(sv[i][0], sv[i][1]), fmaxf(sv[i][2], sv[i][3]));
      mx = fmaxf(mx, __shfl_xor_sync(0xffffffffu, mx, 1));
      mx = fmaxf(mx, __shfl_xor_sync(0xffffffffu, mx, 2));
      mx = fmaxf(mx, __shfl_xor_sync(0xffffffffu, mx, 4));
      mx = fmaxf(mx, __shfl_xor_sync(0xffffffffu, mx, 8));
      float mnew = fmaxf(m_r[i], mx);
      float s = 0.f;
#pragma unroll
      for (int j = 0; j < 4; j++) {
        float p = __expf(sv[i][j] - mnew);
        sv[i][j] = p;
        s += p;
      }
      s += __shfl_xor_sync(0xffffffffu, s, 1);
      s += __shfl_xor_sync(0xffffffffu, s, 2);
      s += __shfl_xor_sync(0xffffffffu, s, 4);
      s += __shfl_xor_sync(0xffffffffu, s, 8);
      c_r[i] = __expf(m_r[i] - mnew);
      m_r[i] = mnew;
      l_r[i] = l_r[i] * c_r[i] + s;
    }
    // write P transposed into Ks: PT[s][t]
#pragma unroll
    for (int i = 0; i < 4; i++)
#pragma unroll
      for (int j = 0; j < 4; j++)
        Ks[swz(cloc + j, tloc + i)] = sv[i][j];
    __syncthreads();

    // ---- O phase with 1-step prefetch ----
#pragma unroll
    for (int i = 0; i < 4; i++) {
      u64 cd = fpack2(c_r[i], c_r[i]);
      accO2[i][0] = fmul2(accO2[i][0], cd);
      accO2[i][1] = fmul2(accO2[i][1], cd);
    }
    ulonglong2 ew0 = *(ulonglong2*)&Es[swz(tloc + 0, cloc)];
    ulonglong2 ew1 = *(ulonglong2*)&Es[swz(tloc + 1, cloc)];
    ulonglong2 ew2 = *(ulonglong2*)&Es[swz(tloc + 2, cloc)];
    ulonglong2 ew3 = *(ulonglong2*)&Es[swz(tloc + 3, cloc)];
    ulonglong2 vd = *(ulonglong2*)&Vs[swz(63, cloc)];
    float4 p4 = *(float4*)&Ks[swz(63, tloc)];
#pragma unroll 4
    for (int s5 = 0; s5 < 64; s5++) {
      const int s = 63 - s5;
      ulonglong2 vdn = vd;
      float4 p4n = p4;
      if (s5 < 63) {
        vdn = *(ulonglong2*)&Vs[swz(s - 1, cloc)];
        p4n = *(float4*)&Ks[swz(s - 1, tloc)];
      }
      ulonglong2 ew3n = *(ulonglong2*)&Es[swz(tloc + 4 + s5, cloc)];
      u64 pd;
      pd = fpack2(p4.x, p4.x);
      accO2[0][0] = ffma2(pd, fadd2(vd.x, ew0.x), accO2[0][0]);
      accO2[0][1] = ffma2(pd, fadd2(vd.y, ew0.y), accO2[0][1]);
      pd = fpack2(p4.y, p4.y);
      accO2[1][0] = ffma2(pd, fadd2(vd.x, ew1.x), accO2[1][0]);
      accO2[1][1] = ffma2(pd, fadd2(vd.y, ew1.y), accO2[1][1]);
      pd = fpack2(p4.z, p4.z);
      accO2[2][0] = ffma2(pd, fadd2(vd.x, ew2.x), accO2[2][0]);
      accO2[2][1] = ffma2(pd, fadd2(vd.y, ew2.y), accO2[2][1]);
      pd = fpack2(p4.w, p4.w);
      accO2[3][0] = ffma2(pd, fadd2(vd.x, ew3.x), accO2[3][0]);
      accO2[3][1] = ffma2(pd, fadd2(vd.y, ew3.y), accO2[3][1]);
      ew0 = ew1; ew1 = ew2; ew2 = ew3; ew3 = ew3n;
      vd = vdn; p4 = p4n;
    }
  }

  // epilogue: normalize, split to bf16 hi/lo, write yh/yl
#pragma unroll
  for (int i = 0; i < 4; i++) {
    float linv = 1.f / l_r[i];
    float o[4];
    funpack2(o[0], o[1], accO2[i][0]);
    funpack2(o[2], o[3], accO2[i][1]);
    size_t off = ((size_t)(b * TSEQ + t0 + tloc + i)) * CDIM + h * 64 + cloc;
    __nv_bfloat16 hh[4], ll[4];
#pragma unroll
    for (int j = 0; j < 4; j++) {
      float v = o[j] * linv;
      hh[j] = __float2bfloat16_rn(v);
      ll[j] = __float2bfloat16_rn(v - __bfloat162float(hh[j]));
    }
    *(__nv_bfloat162*)&yh[off]     = __nv_bfloat162(hh[0], hh[1]);
    *(__nv_bfloat162*)&yh[off + 2] = __nv_bfloat162(hh[2], hh[3]);
    *(__nv_bfloat162*)&yl[off]     = __nv_bfloat162(ll[0], ll[1]);
    *(__nv_bfloat162*)&yl[off + 2] = __nv_bfloat162(ll[2], ll[3]);
  }
}

// ---------------------------------------------------------------------------
extern "C" void kernel_launch(void* const* d_in, const int* in_sizes, int n_in,
                              void* d_out, int out_size) {
  const float* x      = (const float*)d_in[0];
  const float* w_attn = (const float*)d_in[1];
  const float* w_proj = (const float*)d_in[2];
  const float* embk   = (const float*)d_in[3];
  const float* embv   = (const float*)d_in[4];
  float* out = (float*)d_out;

  float *qkv, *G;
  __nv_bfloat16 *xh, *xl, *wah, *wal, *wph, *wpl, *yh, *yl, *qph, *qpl, *ebh, *ebl;
  cudaGetSymbolAddress((void**)&qkv, g_qkv);
  cudaGetSymbolAddress((void**)&G,   g_G);
  cudaGetSymbolAddress((void**)&xh,  g_xh);  cudaGetSymbolAddress((void**)&xl, g_xl);
  cudaGetSymbolAddress((void**)&wah, g_wah); cudaGetSymbolAddress((void**)&wal, g_wal);
  cudaGetSymbolAddress((void**)&wph, g_wph); cudaGetSymbolAddress((void**)&wpl, g_wpl);
  cudaGetSymbolAddress((void**)&yh,  g_yh);  cudaGetSymbolAddress((void**)&yl, g_yl);
  cudaGetSymbolAddress((void**)&qph, g_qph); cudaGetSymbolAddress((void**)&qpl, g_qpl);
  cudaGetSymbolAddress((void**)&ebh, g_ebh); cudaGetSymbolAddress((void**)&ebl, g_ebl);

  const int M = BSZ * TSEQ;
  const int n4 = M * CDIM / 4;

  split_kernel<<<(n4 + 255) / 256, 256>>>(x, xh, xl, n4);
  splitT_kernel<<<dim3(3 * CDIM / 32, CDIM / 32), dim3(32, 8)>>>(w_attn, wah, wal,
                                                                 CDIM, 3 * CDIM);
  splitT_kernel<<<dim3(CDIM / 32, CDIM / 32), dim3(32, 8)>>>(w_proj, wph, wpl,
                                                             CDIM, CDIM);
  split_kernel<<<(TSEQ * DHEAD / 4 + 255) / 256, 256>>>(embk, ebh, ebl,
                                                        TSEQ * DHEAD / 4);

  cudaFuncSetAttribute(gemm_kernel,
                       cudaFuncAttributeMaxDynamicSharedMemorySize, G_SMEM);
  // QKV: [4096,1024] @ [1024,3072]; Q third also emitted as packed bf16 hi/lo
  gemm_kernel<<<dim3(3 * CDIM / 256, M / 128), 256, G_SMEM>>>(
      xh, xl, wah, wal, x, w_attn, qkv, qph, qpl, 0, M, 3 * CDIM, CDIM);

  // G = Qpack @ embk^T (M=65536, N=1024, K=64), triangular (early-exit + masked)
  gemm_kernel<<<dim3(TSEQ / 256, (BSZ * NHEAD * TSEQ) / 128), 256, G_SMEM>>>(
      qph, qpl, ebh, ebl, qkv, w_attn, G, (__nv_bfloat16*)nullptr,
      (__nv_bfloat16*)nullptr, 1, BSZ * NHEAD * TSEQ, TSEQ, DHEAD);

  cudaFuncSetAttribute(attn_kernel, cudaFuncAttributeMaxDynamicSharedMemorySize,
                       ATT_SMEM_BYTES);
  attn_kernel<<<dim3(TSEQ / 64, NHEAD, BSZ), 256, ATT_SMEM_BYTES>>>(qkv, G, embv,
                                                                    yh, yl);

  // Projection: [4096,1024] @ [1024,1024]
  gemm_kernel<<<dim3(CDIM / 256, M / 128), 256, G_SMEM>>>(
      yh, yl, wph, wpl, qkv, w_proj, out, (__nv_bfloat16*)nullptr,
      (__nv_bfloat16*)nullptr, 0, M, CDIM, CDIM);
}

// round 17
// speedup vs baseline: 1.5352x; 1.5352x over previous
#include <cuda_runtime.h>
#include <cuda_bf16.h>
#include <math.h>

#define BSZ   4
#define TSEQ  1024
#define CDIM  1024
#define NHEAD 16
#define DHEAD 64

typedef unsigned long long u64;

#if defined(__CUDA_ARCH_FEAT_SM103_ALL) || \
    (defined(__CUDA_ARCH_SPECIFIC__) && (__CUDA_ARCH_SPECIFIC__ == 1030))
#define HAS_TCGEN05 1
#else
#define HAS_TCGEN05 0
#endif

// ---------------- scratch (allocation-free: __device__ globals) -------------
__device__ float g_qkv[BSZ * TSEQ * 3 * CDIM];
__device__ float g_G[BSZ * NHEAD * TSEQ * TSEQ];          // 268MB: q_t . embk[d]
__device__ __nv_bfloat16 g_xh[BSZ * TSEQ * CDIM], g_xl[BSZ * TSEQ * CDIM];
__device__ __nv_bfloat16 g_wah[3 * CDIM * CDIM], g_wal[3 * CDIM * CDIM]; // [N,K]
__device__ __nv_bfloat16 g_wph[CDIM * CDIM],     g_wpl[CDIM * CDIM];     // [N,K]
__device__ __nv_bfloat16 g_yh[BSZ * TSEQ * CDIM], g_yl[BSZ * TSEQ * CDIM];
__device__ __nv_bfloat16 g_qph[BSZ * NHEAD * TSEQ * DHEAD];
__device__ __nv_bfloat16 g_qpl[BSZ * NHEAD * TSEQ * DHEAD];
__device__ __nv_bfloat16 g_ebh[TSEQ * DHEAD], g_ebl[TSEQ * DHEAD];

// ---------------- packed f32x2 helpers --------------------------------------
__device__ __forceinline__ u64 ffma2(u64 a, u64 b, u64 c) {
  u64 d; asm("fma.rn.f32x2 %0, %1, %2, %3;" : "=l"(d) : "l"(a), "l"(b), "l"(c));
  return d;
}
__device__ __forceinline__ u64 fadd2(u64 a, u64 b) {
  u64 d; asm("add.rn.f32x2 %0, %1, %2;" : "=l"(d) : "l"(a), "l"(b));
  return d;
}
__device__ __forceinline__ u64 fmul2(u64 a, u64 b) {
  u64 d; asm("mul.rn.f32x2 %0, %1, %2;" : "=l"(d) : "l"(a), "l"(b));
  return d;
}
__device__ __forceinline__ u64 fpack2(float lo, float hi) {
  u64 d; asm("mov.b64 %0, {%1, %2};" : "=l"(d) : "f"(lo), "f"(hi));
  return d;
}
__device__ __forceinline__ void funpack2(float& lo, float& hi, u64 d) {
  asm("mov.b64 {%0, %1}, %2;" : "=f"(lo), "=f"(hi) : "l"(d));
}

// ---------------- generic plumbing ------------------------------------------
__device__ __forceinline__ unsigned smem_u32(const void* p) {
  unsigned a;
  asm("{ .reg .u64 t; cvta.to.shared.u64 t, %1; cvt.u32.u64 %0, t; }"
      : "=r"(a) : "l"(p));
  return a;
}
__device__ __forceinline__ unsigned elect_one() {
  unsigned p;
  asm volatile("{ .reg .pred P; elect.sync _|P, 0xFFFFFFFF; selp.b32 %0,1,0,P; }"
               : "=r"(p));
  return p;
}
__device__ __forceinline__ void cp_async16(unsigned dst, const void* src) {
  asm volatile("cp.async.cg.shared.global [%0], [%1], 16;"
               :: "r"(dst), "l"(src) : "memory");
}
#define CP_COMMIT() asm volatile("cp.async.commit_group;" ::: "memory")
#define CP_WAIT(n)  asm volatile("cp.async.wait_group %0;" :: "n"(n) : "memory")

__device__ __forceinline__ void mbar_init(unsigned a, unsigned cnt) {
  asm volatile("mbarrier.init.shared.b64 [%0], %1;" :: "r"(a), "r"(cnt) : "memory");
}
__device__ __forceinline__ void mbar_wait(unsigned a, unsigned phase) {
  asm volatile(
      "{\n\t.reg .pred P;\n\t"
      "W_%=:\n\t"
      "mbarrier.try_wait.parity.acquire.cta.shared::cta.b64 P, [%0], %1, 0x989680;\n\t"
      "@!P bra W_%=;\n\t}"
      :: "r"(a), "r"(phase) : "memory");
}

#define SWZ128(o) ((o) ^ (((o) >> 3) & 0x70))
__device__ __forceinline__ u64 make_desc(unsigned addr) {
  const u64 base = (2ull << 61) | (1ull << 46) | (64ull << 32) | (1ull << 16);
  return base | ((u64)(addr >> 4) & 0x3FFF);
}
// idesc: c=F32, a=BF16, b=BF16, M=128, N=256
#define GEMM_IDESC ((1u<<4)|(1u<<7)|(1u<<10)|((256u/8)<<17)|((128u/16)<<24))

// ---------------- tcgen05 wrappers (sm_103a pass only) ----------------------
#if HAS_TCGEN05
__device__ __forceinline__ void tmem_alloc(unsigned smem_dst, unsigned ncols) {
  asm volatile("tcgen05.alloc.cta_group::1.sync.aligned.shared::cta.b32 [%0], %1;"
               :: "r"(smem_dst), "r"(ncols) : "memory");
}
__device__ __forceinline__ void tmem_dealloc(unsigned tmem, unsigned ncols) {
  asm volatile("tcgen05.dealloc.cta_group::1.sync.aligned.b32 %0, %1;"
               :: "r"(tmem), "r"(ncols));
}
__device__ __forceinline__ void tmem_relinquish() {
  asm volatile("tcgen05.relinquish_alloc_permit.cta_group::1.sync.aligned;");
}
__device__ __forceinline__ void tc_commit(unsigned mbar) {
  asm volatile(
      "tcgen05.commit.cta_group::1.mbarrier::arrive::one.shared::cluster.b64 [%0];"
      :: "r"(mbar) : "memory");
}
#define TC_FENCE_AFTER()  asm volatile("tcgen05.fence::after_thread_sync;" ::: "memory")
#define TC_WAIT_LD()      asm volatile("tcgen05.wait::ld.sync.aligned;" ::: "memory")

__device__ __forceinline__ void mma_f16_ss(unsigned d_tmem, u64 a_desc, u64 b_desc,
                                           unsigned idesc, unsigned enable) {
  asm volatile(
      "{\n\t.reg .pred p;\n\tsetp.ne.u32 p, %4, 0;\n\t"
      "tcgen05.mma.cta_group::1.kind::f16 [%0], %1, %2, %3, {%5,%5,%5,%5}, p;\n\t}"
      :: "r"(d_tmem), "l"(a_desc), "l"(b_desc), "r"(idesc), "r"(enable), "r"(0u)
      : "memory");
}
__device__ __forceinline__ void tmem_ld32(unsigned* r, unsigned addr) {
  asm volatile(
      "tcgen05.ld.sync.aligned.32x32b.x32.b32 "
      "{%0,%1,%2,%3,%4,%5,%6,%7,%8,%9,%10,%11,%12,%13,%14,%15,"
      "%16,%17,%18,%19,%20,%21,%22,%23,%24,%25,%26,%27,%28,%29,%30,%31}, [%32];"
      : "=r"(r[0]),"=r"(r[1]),"=r"(r[2]),"=r"(r[3]),"=r"(r[4]),"=r"(r[5]),
        "=r"(r[6]),"=r"(r[7]),"=r"(r[8]),"=r"(r[9]),"=r"(r[10]),"=r"(r[11]),
        "=r"(r[12]),"=r"(r[13]),"=r"(r[14]),"=r"(r[15]),"=r"(r[16]),"=r"(r[17]),
        "=r"(r[18]),"=r"(r[19]),"=r"(r[20]),"=r"(r[21]),"=r"(r[22]),"=r"(r[23]),
        "=r"(r[24]),"=r"(r[25]),"=r"(r[26]),"=r"(r[27]),"=r"(r[28]),"=r"(r[29]),
        "=r"(r[30]),"=r"(r[31])
      : "r"(addr));
}
#endif  // HAS_TCGEN05

// ---------------------------------------------------------------------------
// Unified GEMM: 128x256 tile, tcgen05 bf16x3 on sm_103a, FFMA2 fp32 fallback.
// Works for NKT=1 (K=64) too.
// ---------------------------------------------------------------------------
#define A_TILE  (128 * 64 * 2)
#define B_TILE  (256 * 64 * 2)
#define G_BUF   (2 * A_TILE + 2 * B_TILE)
#define G_SMEM  (1024 + 2 * G_BUF)

__global__ void __launch_bounds__(256) gemm_kernel(
    const __nv_bfloat16* __restrict__ Ah, const __nv_bfloat16* __restrict__ Al,
    const __nv_bfloat16* __restrict__ Bh, const __nv_bfloat16* __restrict__ Bl,
    const float* __restrict__ Af, const float* __restrict__ Bf,
    float* __restrict__ C, int M, int N, int K) {
  extern __shared__ char smem[];
  const int tid = threadIdx.x;
  const int brow = blockIdx.y * 128, bcol0 = blockIdx.x * 256;

#if HAS_TCGEN05
  const unsigned sb = smem_u32(smem);
  const int wid = tid >> 5, lid = tid & 31;
  const int NKT = K >> 6;
  const unsigned mb0 = sb + 16, mb1 = sb + 24;
  const unsigned tiles = sb + 1024;

  if (tid == 0) { mbar_init(mb0, 1); mbar_init(mb1, 1); }
  if (wid == 0) { tmem_alloc(sb, 256); tmem_relinquish(); }
  __syncthreads();
  unsigned tmem;
  asm volatile("ld.shared.b32 %0, [%1];" : "=r"(tmem) : "r"(sb));

  auto stage1 = [&](unsigned dstbase, const __nv_bfloat16* src, int nrows) {
    const int lines = nrows * 8;
#pragma unroll 8
    for (int i = tid; i < lines; i += 256) {
      int r = i >> 3, c = i & 7;
      cp_async16(dstbase + SWZ128(r * 128 + c * 16), src + (size_t)r * K + c * 8);
    }
  };
  auto stage = [&](int buf, int kt) {
    unsigned base = tiles + buf * G_BUF;
    stage1(base,                       Ah + (size_t)brow * K + kt * 64, 128);
    stage1(base + A_TILE,              Al + (size_t)brow * K + kt * 64, 128);
    stage1(base + 2 * A_TILE,          Bh + (size_t)bcol0 * K + kt * 64, 256);
    stage1(base + 2 * A_TILE + B_TILE, Bl + (size_t)bcol0 * K + kt * 64, 256);
  };

  stage(0, 0);
  CP_COMMIT();
  int ph0 = 0, ph1 = 0;

  for (int kt = 0; kt < NKT; kt++) {
    const int buf = kt & 1;
    if (kt > 0) {
      if (((kt - 1) & 1) == 0) { mbar_wait(mb0, ph0 & 1); ph0++; }
      else                     { mbar_wait(mb1, ph1 & 1); ph1++; }
    }
    if (kt + 1 < NKT) { stage(buf ^ 1, kt + 1); CP_COMMIT(); CP_WAIT(1); }
    else              { CP_WAIT(0); }
    __syncthreads();

    if (wid == 0 && elect_one()) {
      asm volatile("fence.proxy.async.shared::cta;" ::: "memory");
      unsigned base = tiles + buf * G_BUF;
      u64 dAh = make_desc(base),              dAl = make_desc(base + A_TILE);
      u64 dBh = make_desc(base + 2 * A_TILE), dBl = make_desc(base + 2 * A_TILE + B_TILE);
      u64 da[3] = {dAh, dAl, dAh};
      u64 db[3] = {dBh, dBh, dBl};
#pragma unroll
      for (int p = 0; p < 3; p++)
#pragma unroll
        for (int ks = 0; ks < 4; ks++)
          mma_f16_ss(tmem, da[p] + ks * 2, db[p] + ks * 2, GEMM_IDESC,
                     !(kt == 0 && p == 0 && ks == 0));
      tc_commit(buf == 0 ? mb0 : mb1);
    }
  }
  if (((NKT - 1) & 1) == 0) { mbar_wait(mb0, ph0 & 1); }
  else                      { mbar_wait(mb1, ph1 & 1); }
  TC_FENCE_AFTER();

  if (wid < 4) {
    const size_t row = (size_t)brow + wid * 32 + lid;
#pragma unroll
    for (int cb = 0; cb < 256; cb += 32) {
      unsigned r[32];
      tmem_ld32(r, tmem + cb);
      TC_WAIT_LD();
      float* dst = &C[row * N + bcol0 + cb];
#pragma unroll
      for (int c = 0; c < 32; c += 4)
        *(float4*)&dst[c] = make_float4(__uint_as_float(r[c]), __uint_as_float(r[c+1]),
                                        __uint_as_float(r[c+2]), __uint_as_float(r[c+3]));
    }
  }
  __syncthreads();
  if (wid == 0) tmem_dealloc(tmem, 256);

#else  // fallback: fp32 FFMA2 SGEMM over the two 128-col halves
  float (*As)[16][132] = reinterpret_cast<float(*)[16][132]>(smem);
  float (*Bs)[16][132] = reinterpret_cast<float(*)[16][132]>(smem + 2 * 16 * 132 * 4);
  const int ty = tid >> 4, tx = tid & 15;
  const int ar0 = tid >> 2,          ac0 = (tid & 3) * 4;
  const int ar1 = (tid + 256) >> 2,  ac1 = ((tid + 256) & 3) * 4;
  const int br0 = tid >> 5,          bc0 = (tid & 31) * 4;
  const int br1 = (tid + 256) >> 5,  bc1 = ((tid + 256) & 31) * 4;

  for (int half = 0; half < 2; half++) {
    const int bcol = bcol0 + half * 128;
    __syncthreads();
    u64 acc2[8][4];
#pragma unroll
    for (int i = 0; i < 8; i++)
#pragma unroll
      for (int j = 0; j < 4; j++) acc2[i][j] = 0ull;

    {
      float4 a0 = *(const float4*)&Af[(size_t)(brow + ar0) * K + ac0];
      float4 a1 = *(const float4*)&Af[(size_t)(brow + ar1) * K + ac1];
      As[0][ac0 + 0][ar0] = a0.x; As[0][ac0 + 1][ar0] = a0.y;
      As[0][ac0 + 2][ar0] = a0.z; As[0][ac0 + 3][ar0] = a0.w;
      As[0][ac1 + 0][ar1] = a1.x; As[0][ac1 + 1][ar1] = a1.y;
      As[0][ac1 + 2][ar1] = a1.z; As[0][ac1 + 3][ar1] = a1.w;
      *(float4*)&Bs[0][br0][bc0] = *(const float4*)&Bf[(size_t)br0 * N + bcol + bc0];
      *(float4*)&Bs[0][br1][bc1] = *(const float4*)&Bf[(size_t)br1 * N + bcol + bc1];
    }
    __syncthreads();

    int buf = 0;
    for (int k0 = 0; k0 < K; k0 += 16) {
      const bool has_next = (k0 + 16) < K;
      float4 pa0, pa1, pb0, pb1;
      if (has_next) {
        pa0 = *(const float4*)&Af[(size_t)(brow + ar0) * K + k0 + 16 + ac0];
        pa1 = *(const float4*)&Af[(size_t)(brow + ar1) * K + k0 + 16 + ac1];
        pb0 = *(const float4*)&Bf[(size_t)(k0 + 16 + br0) * N + bcol + bc0];
        pb1 = *(const float4*)&Bf[(size_t)(k0 + 16 + br1) * N + bcol + bc1];
      }
#pragma unroll
      for (int kk = 0; kk < 16; kk++) {
        float a[8];
        *(float4*)&a[0] = *(float4*)&As[buf][kk][ty * 8];
        *(float4*)&a[4] = *(float4*)&As[buf][kk][ty * 8 + 4];
        u64 b2[4];
        *(ulonglong2*)&b2[0] = *(ulonglong2*)&Bs[buf][kk][tx * 4];
        *(ulonglong2*)&b2[2] = *(ulonglong2*)&Bs[buf][kk][64 + tx * 4];
        u64 ad[8];
#pragma unroll
        for (int i = 0; i < 8; i++) ad[i] = fpack2(a[i], a[i]);
#pragma unroll
        for (int i = 0; i < 8; i++)
#pragma unroll
          for (int j = 0; j < 4; j++) acc2[i][j] = ffma2(ad[i], b2[j], acc2[i][j]);
      }
      if (has_next) {
        int nb = buf ^ 1;
        As[nb][ac0 + 0][ar0] = pa0.x; As[nb][ac0 + 1][ar0] = pa0.y;
        As[nb][ac0 + 2][ar0] = pa0.z; As[nb][ac0 + 3][ar0] = pa0.w;
        As[nb][ac1 + 0][ar1] = pa1.x; As[nb][ac1 + 1][ar1] = pa1.y;
        As[nb][ac1 + 2][ar1] = pa1.z; As[nb][ac1 + 3][ar1] = pa1.w;
        *(float4*)&Bs[nb][br0][bc0] = pb0;
        *(float4*)&Bs[nb][br1][bc1] = pb1;
        __syncthreads();
        buf = nb;
      }
    }
#pragma unroll
    for (int i = 0; i < 8; i++) {
      size_t r = (size_t)(brow + ty * 8 + i) * N + bcol;
      *(ulonglong2*)&C[r + tx * 4]      = make_ulonglong2(acc2[i][0], acc2[i][1]);
      *(ulonglong2*)&C[r + 64 + tx * 4] = make_ulonglong2(acc2[i][2], acc2[i][3]);
    }
  }
#endif
}

// ---------------------------------------------------------------------------
__global__ void __launch_bounds__(256) split_kernel(
    const float* __restrict__ src, __nv_bfloat16* __restrict__ h,
    __nv_bfloat16* __restrict__ l, int n4) {
  int i = blockIdx.x * 256 + threadIdx.x;
  if (i >= n4) return;
  float4 v = ((const float4*)src)[i];
  __nv_bfloat16 h0 = __float2bfloat16_rn(v.x), h1 = __float2bfloat16_rn(v.y);
  __nv_bfloat16 h2 = __float2bfloat16_rn(v.z), h3 = __float2bfloat16_rn(v.w);
  __nv_bfloat16 l0 = __float2bfloat16_rn(v.x - __bfloat162float(h0));
  __nv_bfloat16 l1 = __float2bfloat16_rn(v.y - __bfloat162float(h1));
  __nv_bfloat16 l2 = __float2bfloat16_rn(v.z - __bfloat162float(h2));
  __nv_bfloat16 l3 = __float2bfloat16_rn(v.w - __bfloat162float(h3));
  ((__nv_bfloat162*)h)[i * 2]     = __nv_bfloat162(h0, h1);
  ((__nv_bfloat162*)h)[i * 2 + 1] = __nv_bfloat162(h2, h3);
  ((__nv_bfloat162*)l)[i * 2]     = __nv_bfloat162(l0, l1);
  ((__nv_bfloat162*)l)[i * 2 + 1] = __nv_bfloat162(l2, l3);
}

__global__ void __launch_bounds__(256) splitT_kernel(
    const float* __restrict__ w, __nv_bfloat16* __restrict__ h,
    __nv_bfloat16* __restrict__ l, int K, int N) {
  __shared__ float t[32][33];
  int n0 = blockIdx.x * 32, k0 = blockIdx.y * 32;
  int tx = threadIdx.x, ty = threadIdx.y;
#pragma unroll
  for (int i = 0; i < 32; i += 8)
    t[ty + i][tx] = w[(size_t)(k0 + ty + i) * N + n0 + tx];
  __syncthreads();
#pragma unroll
  for (int i = 0; i < 32; i += 8) {
    float v = t[tx][ty + i];
    __nv_bfloat16 hh = __float2bfloat16_rn(v);
    __nv_bfloat16 ll = __float2bfloat16_rn(v - __bfloat162float(hh));
    size_t o = (size_t)(n0 + ty + i) * K + k0 + tx;
    h[o] = hh; l[o] = ll;
  }
}

// Pack the Q part of qkv into [b*H+h][t][64] bf16 hi/lo (A operand for the
// G GEMM: G[bht, d] = q . embk[d]).
__global__ void __launch_bounds__(256) qpack_kernel(
    const float* __restrict__ qkv, __nv_bfloat16* __restrict__ qh,
    __nv_bfloat16* __restrict__ ql) {
  int idx = blockIdx.x * 256 + threadIdx.x;          // over 65536*16
  int row = idx >> 4;
  int dc = (idx & 15) << 2;
  int bh = row >> 10, t = row & 1023;
  int b = bh >> 4, hh = bh & 15;
  float4 v = *(const float4*)&qkv[((size_t)(b * TSEQ + t)) * (3 * CDIM) + hh * 64 + dc];
  __nv_bfloat16 h0 = __float2bfloat16_rn(v.x), h1 = __float2bfloat16_rn(v.y);
  __nv_bfloat16 h2 = __float2bfloat16_rn(v.z), h3 = __float2bfloat16_rn(v.w);
  __nv_bfloat16 l0 = __float2bfloat16_rn(v.x - __bfloat162float(h0));
  __nv_bfloat16 l1 = __float2bfloat16_rn(v.y - __bfloat162float(h1));
  __nv_bfloat16 l2 = __float2bfloat16_rn(v.z - __bfloat162float(h2));
  __nv_bfloat16 l3 = __float2bfloat16_rn(v.w - __bfloat162float(h3));
  size_t o = (size_t)row * 64 + dc;
  *(__nv_bfloat162*)&qh[o]     = __nv_bfloat162(h0, h1);
  *(__nv_bfloat162*)&qh[o + 2] = __nv_bfloat162(h2, h3);
  *(__nv_bfloat162*)&ql[o]     = __nv_bfloat162(l0, l1);
  *(__nv_bfloat162*)&ql[o + 2] = __nv_bfloat162(l2, l3);
}

// ---------------------------------------------------------------------------
// Flash attention with RPE (R11 verified-optimal structure):
//  - score-side RPE from precomputed fp32 G[bht][d] (coalesced LDG gather)
//  - Es buffer holds only embv, staged at tile top
//  - register-resident softmax (16-lane row groups)
//  - P transposed into dead Ks buffer; O phase with rolling Ev window and
//    1-step software prefetch
//  - epilogue writes yh/yl bf16 hi/lo directly (proj consumes them)
// ---------------------------------------------------------------------------
__device__ __forceinline__ int swz(int r, int kk) {
  return r * 64 + ((((kk >> 2) ^ (r >> 2)) & 15) << 2) + (kk & 3);
}

#define ATT_SMEM_FLOATS (3 * 64 * 64 + 128 * 64)
#define ATT_SMEM_BYTES  (ATT_SMEM_FLOATS * 4)

__global__ void __launch_bounds__(256, 2) attn_kernel(
    const float* __restrict__ qkv, const float* __restrict__ G,
    const float* __restrict__ embv,
    __nv_bfloat16* __restrict__ yh, __nv_bfloat16* __restrict__ yl) {
  extern __shared__ float sm[];
  float* Qs  = sm;
  float* Ks  = sm + 64 * 64;
  float* Vs  = sm + 2 * 64 * 64;
  float* Es  = sm + 3 * 64 * 64;

  const int tid = threadIdx.x;
  const int tb = gridDim.x - 1 - blockIdx.x;
  const int h = blockIdx.y, b = blockIdx.z;
  const int t0 = tb * 64;
  const int ty = tid >> 4, tx = tid & 15;
  const int tloc = ty * 4;
  const int cloc = tx * 4;

  const float* Grow[4];
#pragma unroll
  for (int i = 0; i < 4; i++)
    Grow[i] = G + (((size_t)(b * NHEAD + h) * TSEQ) + (t0 + tloc + i)) * TSEQ;

#pragma unroll
  for (int it = 0; it < 4; it++) {
    int g = it * 256 + tid;
    int t = g >> 4, kc = (g & 15) << 2;
    *(float4*)&Qs[swz(t, kc)] =
        *(const float4*)&qkv[(b * TSEQ + t0 + t) * (3 * CDIM) + h * 64 + kc];
  }

  float m_r[4], l_r[4];
#pragma unroll
  for (int i = 0; i < 4; i++) { m_r[i] = -1e30f; l_r[i] = 0.f; }

  u64 accO2[4][2];
#pragma unroll
  for (int i = 0; i < 4; i++) { accO2[i][0] = 0ull; accO2[i][1] = 0ull; }

  for (int sb = 0; sb <= tb; sb++) {
    const int s0 = sb * 64;
    const int diff = t0 - s0;
    __syncthreads();

#pragma unroll
    for (int it = 0; it < 4; it++) {
      int g = it * 256 + tid;
      int s = g >> 4, kc = (g & 15) << 2;
      const float* src = &qkv[(b * TSEQ + s0 + s) * (3 * CDIM) + h * 64 + kc];
      float4 kv = *(const float4*)(src + CDIM);
      float4 vv = *(const float4*)(src + 2 * CDIM);
      kv.x *= 0.125f; kv.y *= 0.125f; kv.z *= 0.125f; kv.w *= 0.125f;
      *(float4*)&Ks[swz(s, kc)] = kv;
      *(float4*)&Vs[swz(s, kc)] = vv;
    }
#pragma unroll
    for (int it = 0; it < 8; it++) {
      int g = it * 256 + tid;
      int j = g >> 4, kc = (g & 15) << 2;
      int rel = diff - 63 + j;
      float4 v = make_float4(0.f, 0.f, 0.f, 0.f);
      if (rel >= 0 && rel < TSEQ) v = *(const float4*)&embv[rel * 64 + kc];
      *(float4*)&Es[swz(j, kc)] = v;
    }
    // gather G band while staging is in flight (independent LDGs)
    float gv[4][4];
    if (sb < tb) {
#pragma unroll
      for (int i = 0; i < 4; i++) {
        int Di = diff + tloc + i - cloc;
#pragma unroll
        for (int j = 0; j < 4; j++) gv[i][j] = Grow[i][Di - j];
      }
    } else {
#pragma unroll
      for (int i = 0; i < 4; i++) {
        int Di = diff + tloc + i - cloc;
#pragma unroll
        for (int j = 0; j < 4; j++) {
          int d = Di - j;
          gv[i][j] = (d >= 0) ? Grow[i][d] : 0.f;
        }
      }
    }
    __syncthreads();

    // ---- S phase: S[t,s] = q . k_scaled (+ G bias) ----
    u64 acc2[4][4];
#pragma unroll
    for (int i = 0; i < 4; i++)
#pragma unroll
      for (int j = 0; j < 4; j++) acc2[i][j] = 0ull;

#pragma unroll 4
    for (int kk = 0; kk < 64; kk += 4) {
      ulonglong2 qd[4], kd[4];
#pragma unroll
      for (int i = 0; i < 4; i++) qd[i] = *(ulonglong2*)&Qs[swz(tloc + i, kk)];
#pragma unroll
      for (int j = 0; j < 4; j++) kd[j] = *(ulonglong2*)&Ks[swz(cloc + j, kk)];
#pragma unroll
      for (int i = 0; i < 4; i++)
#pragma unroll
        for (int j = 0; j < 4; j++) {
          acc2[i][j] = ffma2(qd[i].x, kd[j].x, acc2[i][j]);
          acc2[i][j] = ffma2(qd[i].y, kd[j].y, acc2[i][j]);
        }
    }
    float sv[4][4];
#pragma unroll
    for (int i = 0; i < 4; i++)
#pragma unroll
      for (int j = 0; j < 4; j++) {
        float lo, hi; funpack2(lo, hi, acc2[i][j]);
        bool masked = (sb == tb) && (cloc + j > tloc + i);
        sv[i][j] = masked ? -1e30f : (lo + hi + gv[i][j]);
      }
    __syncthreads();   // all S-phase Ks reads done -> Ks reusable as PT

    // ---- register softmax (16-lane row groups) ----
    float c_r[4];
#pragma unroll
    for (int i = 0; i < 4; i++) {
      float mx = fmaxf(fmaxf(sv[i][0], sv[i][1]), fmaxf(sv[i][2], sv[i][3]));
      mx = fmaxf(mx, __shfl_xor_sync(0xffffffffu, mx, 1));
      mx = fmaxf(mx, __shfl_xor_sync(0xffffffffu, mx, 2));
      mx = fmaxf(mx, __shfl_xor_sync(0xffffffffu, mx, 4));
      mx = fmaxf(mx, __shfl_xor_sync(0xffffffffu, mx, 8));
      float mnew = fmaxf(m_r[i], mx);
      float s = 0.f;
#pragma unroll
      for (int j = 0; j < 4; j++) {
        float p = __expf(sv[i][j] - mnew);
        sv[i][j] = p;
        s += p;
      }
      s += __shfl_xor_sync(0xffffffffu, s, 1);
      s += __shfl_xor_sync(0xffffffffu, s, 2);
      s += __shfl_xor_sync(0xffffffffu, s, 4);
      s += __shfl_xor_sync(0xffffffffu, s, 8);
      c_r[i] = __expf(m_r[i] - mnew);
      m_r[i] = mnew;
      l_r[i] = l_r[i] * c_r[i] + s;
    }
    // write P transposed into Ks: PT[s][t]
#pragma unroll
    for (int i = 0; i < 4; i++)
#pragma unroll
      for (int j = 0; j < 4; j++)
        Ks[swz(cloc + j, tloc + i)] = sv[i][j];
    __syncthreads();

    // ---- O phase with 1-step prefetch ----
#pragma unroll
    for (int i = 0; i < 4; i++) {
      u64 cd = fpack2(c_r[i], c_r[i]);
      accO2[i][0] = fmul2(accO2[i][0], cd);
      accO2[i][1] = fmul2(accO2[i][1], cd);
    }
    ulonglong2 ew0 = *(ulonglong2*)&Es[swz(tloc + 0, cloc)];
    ulonglong2 ew1 = *(ulonglong2*)&Es[swz(tloc + 1, cloc)];
    ulonglong2 ew2 = *(ulonglong2*)&Es[swz(tloc + 2, cloc)];
    ulonglong2 ew3 = *(ulonglong2*)&Es[swz(tloc + 3, cloc)];
    ulonglong2 vd = *(ulonglong2*)&Vs[swz(63, cloc)];
    float4 p4 = *(float4*)&Ks[swz(63, tloc)];
#pragma unroll 4
    for (int s5 = 0; s5 < 64; s5++) {
      const int s = 63 - s5;
      ulonglong2 vdn = vd;
      float4 p4n = p4;
      if (s5 < 63) {
        vdn = *(ulonglong2*)&Vs[swz(s - 1, cloc)];
        p4n = *(float4*)&Ks[swz(s - 1, tloc)];
      }
      ulonglong2 ew3n = *(ulonglong2*)&Es[swz(tloc + 4 + s5, cloc)];
      u64 pd;
      pd = fpack2(p4.x, p4.x);
      accO2[0][0] = ffma2(pd, fadd2(vd.x, ew0.x), accO2[0][0]);
      accO2[0][1] = ffma2(pd, fadd2(vd.y, ew0.y), accO2[0][1]);
      pd = fpack2(p4.y, p4.y);
      accO2[1][0] = ffma2(pd, fadd2(vd.x, ew1.x), accO2[1][0]);
      accO2[1][1] = ffma2(pd, fadd2(vd.y, ew1.y), accO2[1][1]);
      pd = fpack2(p4.z, p4.z);
      accO2[2][0] = ffma2(pd, fadd2(vd.x, ew2.x), accO2[2][0]);
      accO2[2][1] = ffma2(pd, fadd2(vd.y, ew2.y), accO2[2][1]);
      pd = fpack2(p4.w, p4.w);
      accO2[3][0] = ffma2(pd, fadd2(vd.x, ew3.x), accO2[3][0]);
      accO2[3][1] = ffma2(pd, fadd2(vd.y, ew3.y), accO2[3][1]);
      ew0 = ew1; ew1 = ew2; ew2 = ew3; ew3 = ew3n;
      vd = vdn; p4 = p4n;
    }
  }

  // epilogue: normalize, split to bf16 hi/lo, write yh/yl
#pragma unroll
  for (int i = 0; i < 4; i++) {
    float linv = 1.f / l_r[i];
    float o[4];
    funpack2(o[0], o[1], accO2[i][0]);
    funpack2(o[2], o[3], accO2[i][1]);
    size_t off = ((size_t)(b * TSEQ + t0 + tloc + i)) * CDIM + h * 64 + cloc;
    __nv_bfloat16 hh[4], ll[4];
#pragma unroll
    for (int j = 0; j < 4; j++) {
      float v = o[j] * linv;
      hh[j] = __float2bfloat16_rn(v);
      ll[j] = __float2bfloat16_rn(v - __bfloat162float(hh[j]));
    }
    *(__nv_bfloat162*)&yh[off]     = __nv_bfloat162(hh[0], hh[1]);
    *(__nv_bfloat162*)&yh[off + 2] = __nv_bfloat162(hh[2], hh[3]);
    *(__nv_bfloat162*)&yl[off]     = __nv_bfloat162(ll[0], ll[1]);
    *(__nv_bfloat162*)&yl[off + 2] = __nv_bfloat162(ll[2], ll[3]);
  }
}

// ---------------------------------------------------------------------------
extern "C" void kernel_launch(void* const* d_in, const int* in_sizes, int n_in,
                              void* d_out, int out_size) {
  const float* x      = (const float*)d_in[0];
  const float* w_attn = (const float*)d_in[1];
  const float* w_proj = (const float*)d_in[2];
  const float* embk   = (const float*)d_in[3];
  const float* embv   = (const float*)d_in[4];
  float* out = (float*)d_out;

  float *qkv, *G;
  __nv_bfloat16 *xh, *xl, *wah, *wal, *wph, *wpl, *yh, *yl, *qph, *qpl, *ebh, *ebl;
  cudaGetSymbolAddress((void**)&qkv, g_qkv);
  cudaGetSymbolAddress((void**)&G,   g_G);
  cudaGetSymbolAddress((void**)&xh,  g_xh);  cudaGetSymbolAddress((void**)&xl, g_xl);
  cudaGetSymbolAddress((void**)&wah, g_wah); cudaGetSymbolAddress((void**)&wal, g_wal);
  cudaGetSymbolAddress((void**)&wph, g_wph); cudaGetSymbolAddress((void**)&wpl, g_wpl);
  cudaGetSymbolAddress((void**)&yh,  g_yh);  cudaGetSymbolAddress((void**)&yl, g_yl);
  cudaGetSymbolAddress((void**)&qph, g_qph); cudaGetSymbolAddress((void**)&qpl, g_qpl);
  cudaGetSymbolAddress((void**)&ebh, g_ebh); cudaGetSymbolAddress((void**)&ebl, g_ebl);

  const int M = BSZ * TSEQ;
  const int n4 = M * CDIM / 4;

  split_kernel<<<(n4 + 255) / 256, 256>>>(x, xh, xl, n4);
  splitT_kernel<<<dim3(3 * CDIM / 32, CDIM / 32), dim3(32, 8)>>>(w_attn, wah, wal,
                                                                 CDIM, 3 * CDIM);
  splitT_kernel<<<dim3(CDIM / 32, CDIM / 32), dim3(32, 8)>>>(w_proj, wph, wpl,
                                                             CDIM, CDIM);
  split_kernel<<<(TSEQ * DHEAD / 4 + 255) / 256, 256>>>(embk, ebh, ebl,
                                                        TSEQ * DHEAD / 4);

  cudaFuncSetAttribute(gemm_kernel,
                       cudaFuncAttributeMaxDynamicSharedMemorySize, G_SMEM);
  // QKV: [4096,1024] @ [1024,3072]
  gemm_kernel<<<dim3(3 * CDIM / 256, M / 128), 256, G_SMEM>>>(
      xh, xl, wah, wal, x, w_attn, qkv, M, 3 * CDIM, CDIM);

  // pack Q and compute G = Qpack @ embk^T  (M=65536, N=1024, K=64)
  qpack_kernel<<<(BSZ * NHEAD * TSEQ * 16) / 256, 256>>>(qkv, qph, qpl);
  gemm_kernel<<<dim3(TSEQ / 256, (BSZ * NHEAD * TSEQ) / 128), 256, G_SMEM>>>(
      qph, qpl, ebh, ebl, qkv, w_attn, G, BSZ * NHEAD * TSEQ, TSEQ, DHEAD);

  cudaFuncSetAttribute(attn_kernel, cudaFuncAttributeMaxDynamicSharedMemorySize,
                       ATT_SMEM_BYTES);
  attn_kernel<<<dim3(TSEQ / 64, NHEAD, BSZ), 256, ATT_SMEM_BYTES>>>(qkv, G, embv,
                                                                    yh, yl);

  // Projection: [4096,1024] @ [1024,1024]
  gemm_kernel<<<dim3(CDIM / 256, M / 128), 256, G_SMEM>>>(
      yh, yl, wph, wpl, qkv, w_proj, out, M, CDIM, CDIM);
}